// round 13
// baseline (speedup 1.0000x reference)
#include <cuda_runtime.h>
#include <cuda_fp16.h>
#include <math.h>
#include <stdint.h>

#define T_ 4
#define B_ 16
#define C_ 256
#define L_ 2048
#define O_ 512
#define TBCL_ (T_*B_*C_*L_)
#define ZA 0.38079708f
#define ZB 0.55676994f
#define DZ (ZB - ZA)
#define XS 16.0f
#define WSC 128.0f
#define INV_SC (1.0f/2048.0f)

typedef uint32_t u32;

__device__ __forceinline__ u32 smem_u32(const void* p) {
    u32 a;
    asm("{ .reg .u64 t; cvta.to.shared.u64 t, %1; cvt.u32.u64 %0, t; }" : "=r"(a) : "l"(p));
    return a;
}
__device__ __forceinline__ void cp16(u32 dst, const void* src) {
    asm volatile("cp.async.cg.shared.global [%0], [%1], 16;" :: "r"(dst), "l"(src));
}
__device__ __forceinline__ void cp16z(u32 dst, const void* src, bool ok) {
    int sz = ok ? 16 : 0;
    asm volatile("cp.async.cg.shared.global [%0], [%1], 16, %2;" :: "r"(dst), "l"(src), "r"(sz));
}
__device__ __forceinline__ void mma16816(float* c, u32 a0, u32 a1, u32 a2, u32 a3, u32 b0, u32 b1) {
    asm volatile("mma.sync.aligned.m16n8k16.row.col.f32.f16.f16.f32 "
                 "{%0,%1,%2,%3},{%4,%5,%6,%7},{%8,%9},{%0,%1,%2,%3};"
                 : "+f"(c[0]), "+f"(c[1]), "+f"(c[2]), "+f"(c[3])
                 : "r"(a0), "r"(a1), "r"(a2), "r"(a3), "r"(b0), "r"(b1));
}

// ---- device scratch ----
__device__ __half g_s[(size_t)T_*B_*L_*512];   // spikes [tb][l][512] = [u(256)|w(256)]
__device__ __half g_xt[(size_t)T_*B_*L_*512];  // x splits [tb][l][hi(256)|lo(256)], x16
__device__ __half g_w2[512 * 512];             // out-GEMM weights [n][512]
__device__ __half g_wcs[6 * 512 * 256];        // conv w splits [sp][sh][o][c], x128
__device__ float g_base[B_*O_];
__device__ float g_e0[B_*O_];
__device__ float g_e2[B_*O_];

// ---------------- fused prep kernel (block-range dispatch) ----------------
// blocks [0,16): proj+econv per batch
// blocks [16,1040): w2build ; [1040,1552): wsplit ; [1552,34320): xsplit
#define PREP_BLOCKS 34320

__global__ void __launch_bounds__(256) k_prep(
    const float* __restrict__ x, const int* __restrict__ dstep,
    const float* __restrict__ w1, const float* __restrict__ b1,
    const float* __restrict__ w2, const float* __restrict__ b2,
    const float* __restrict__ wp, const float* __restrict__ bp,
    const float* __restrict__ w_conv, const float* __restrict__ b_conv,
    const float* __restrict__ w_skip, const float* __restrict__ w_res) {
    const int blk = blockIdx.x;
    const int tid = threadIdx.x;

    if (blk < 16) {                     // ---- proj + econv for batch b ----
        int b = blk, c = tid;
        __shared__ float h[C_], emb[C_], pr[C_];
        float ds = (float)dstep[b];
        float t1 = ds * w1[c] + b1[c];
        h[c] = t1 / (1.f + expf(-t1));
        __syncthreads();
        float e = b2[c];
        const float* w2r = w2 + c * C_;
        for (int j = 0; j < C_; j++) e += w2r[j] * h[j];
        __syncthreads();
        emb[c] = e;
        __syncthreads();
        float p = bp[c];
        const float* wpr = wp + c * C_;
        for (int j = 0; j < C_; j++) p += wpr[j] * emb[j];
        pr[c] = p;
        __syncthreads();
        #pragma unroll
        for (int oo = 0; oo < 2; oo++) {
            int o = tid + oo * 256;
            float e0 = 0.f, e1 = 0.f, e2 = 0.f;
            const float* wr = w_conv + (size_t)o * C_ * 3;
            #pragma unroll 4
            for (int cc = 0; cc < C_; cc++) {
                float p2 = pr[cc];
                e0 += wr[cc * 3 + 0] * p2;
                e1 += wr[cc * 3 + 1] * p2;
                e2 += wr[cc * 3 + 2] * p2;
            }
            g_base[b * O_ + o] = e0 + e1 + e2 + b_conv[o];
            g_e0[b * O_ + o] = e0;
            g_e2[b * O_ + o] = e2;
        }
    } else if (blk < 1040) {            // ---- w2build ----
        int i = (blk - 16) * 256 + tid;
        int n = i >> 9, kk = i & 511;
        int c = kk & 255, part = kk >> 8;
        float wv = (n < 256) ? w_res[n * C_ + c] : w_skip[(n - 256) * C_ + c];
        g_w2[n * 512 + kk] = __float2half((part ? DZ : ZA) * wv);
    } else if (blk < 1552) {            // ---- wsplit ----
        int i = (blk - 1040) * 256 + tid;
        int o = i >> 8, c = i & 255;
        #pragma unroll
        for (int k = 0; k < 3; k++) {
            float w = w_conv[(o * C_ + c) * 3 + k] * WSC;
            __half h1 = __float2half_rn(w);
            float r1 = w - __half2float(h1);
            __half h2 = __float2half_rn(r1);
            size_t base = ((size_t)k * 512 + o) * 256 + c;
            g_wcs[0 * 393216 + base] = h1;
            g_wcs[1 * 393216 + base] = h2;
        }
    } else {                            // ---- xsplit ----
        __shared__ float tile[32][33];
        int idx = blk - 1552;
        int lt = idx & 63, cb = (idx >> 6) & 7, tb = idx >> 9;
        int c0 = cb * 32, l0 = lt * 32;
        int tx = tid & 31, ty = tid >> 5;
        const float* xb = x + ((size_t)tb * C_ + c0) * L_ + l0;
        #pragma unroll
        for (int i = 0; i < 4; i++)
            tile[ty + i * 8][tx] = xb[(size_t)(ty + i * 8) * L_ + tx];
        __syncthreads();
        __half* dst = g_xt + ((size_t)tb * L_ + l0) * 512 + c0;
        #pragma unroll
        for (int i = 0; i < 4; i++) {
            int l = ty + i * 8;
            float v = tile[tx][l] * XS;
            __half h1 = __float2half_rn(v);
            __half h2 = __float2half_rn(v - __half2float(h1));
            dst[(size_t)l * 512 + tx] = h1;
            dst[(size_t)l * 512 + 256 + tx] = h2;
        }
    }
}

// ---------------- conv1d + LIF via HMMA (fp16 2x2 split, 3 terms) ----------------
// 128-l tile, 512 threads, 1 CTA/SM. grid (16 lt, 4 ot, 16 b).
#define WS_SZ 36864
#define CSTAGE 49344
#define CONV_SMEM (2*CSTAGE + 2*18432)

__global__ void __launch_bounds__(512, 1) k_conv_mma() {
    extern __shared__ char sm[];
    const u32 sb = smem_u32(sm);
    const int lt = blockIdx.x, ot = blockIdx.y, b = blockIdx.z;
    const int l0 = lt * 128;
    const int tid = threadIdx.x, wid = tid >> 5, lane = tid & 31;
    const int wn = wid >> 2, wl = wid & 3;
    const int r4 = lane >> 2, c2 = (lane & 3) * 2;

    __half* su  = (__half*)(sm + 2 * CSTAGE);
    __half* sw_ = (__half*)(sm + 2 * CSTAGE + 18432);

    auto load_step = [&](int step) {
        int t = step >> 4, cc = (step & 15) << 4, s = step & 1;
        u32 wsb = sb + s * CSTAGE;
        #pragma unroll
        for (int j = 0; j < 3; j++) {
            int idx = tid + j * 512;
            int c16 = idx & 1;
            int m = (idx >> 1) & 127;
            int q = idx >> 8;
            int sh = q >> 1, sp = q & 1;
            int o = (m < 64) ? (ot * 64 + m) : (256 + ot * 64 + m - 64);
            const __half* src = g_wcs + (((size_t)(sp * 3 + sh) * 512 + o) << 8) + cc + c16 * 8;
            cp16(wsb + (u32)((q * 128 + m) * 48 + c16 * 16), src);
        }
        const __half* xb = g_xt + ((size_t)(t * B_ + b) * L_) * 512;
        u32 xsb = sb + s * CSTAGE + WS_SZ;
        #pragma unroll
        for (int j = 0; j < 2; j++) {
            int u = tid + j * 512;
            if (u < 520) {
                int li = u >> 2, q = u & 3;
                int sp = q >> 1, h16 = q & 1;
                int gl = l0 - 1 + li;
                bool ok = (gl >= 0 && gl < L_);
                int glc = ok ? gl : 0;
                const __half* src = xb + (size_t)glc * 512 + sp * 256 + cc + h16 * 8;
                cp16z(xsb + (u32)(((sp * 130 + li) * 24 + h16 * 8) * 2), src, ok);
            }
        }
        asm volatile("cp.async.commit_group;" ::: "memory");
    };

    float acc[2][4][4];
    float v[2][2][8];
    #pragma unroll
    for (int m = 0; m < 2; m++)
        #pragma unroll
        for (int j = 0; j < 4; j++)
            #pragma unroll
            for (int e = 0; e < 4; e++) acc[m][j][e] = 0.f;
    #pragma unroll
    for (int g = 0; g < 2; g++)
        #pragma unroll
        for (int h = 0; h < 2; h++)
            #pragma unroll
            for (int e = 0; e < 8; e++) v[g][h][e] = 0.f;

    load_step(0);
    load_step(1);

    const __half one = __float2half(1.f), zero = __float2half(0.f);

    #pragma unroll 1
    for (int step = 0; step < 64; step++) {
        if (step < 62) asm volatile("cp.async.wait_group 1;" ::: "memory");
        else           asm volatile("cp.async.wait_group 0;" ::: "memory");
        __syncthreads();
        int s = step & 1;
        const char* wsb = sm + s * CSTAGE;
        const __half* xs = (const __half*)(sm + s * CSTAGE + WS_SZ);

        #pragma unroll
        for (int sh = 0; sh < 3; sh++) {
            u32 bf0[2][4], bf1[2][4];
            #pragma unroll
            for (int sp = 0; sp < 2; sp++)
                #pragma unroll
                for (int j = 0; j < 4; j++) {
                    const __half* p = xs + (sp * 130 + wl * 32 + j * 8 + r4 + sh) * 24 + c2;
                    bf0[sp][j] = *(const u32*)p;
                    bf1[sp][j] = *(const u32*)(p + 8);
                }
            u32 a[2][2][4];
            #pragma unroll
            for (int sp = 0; sp < 2; sp++)
                #pragma unroll
                for (int m = 0; m < 2; m++) {
                    const __half* p = (const __half*)(wsb + ((sh * 2 + sp) * 128 + m * 64 + wn * 16 + r4) * 48) + c2;
                    a[sp][m][0] = *(const u32*)p;
                    a[sp][m][1] = *(const u32*)(p + 8 * 24);
                    a[sp][m][2] = *(const u32*)(p + 8);
                    a[sp][m][3] = *(const u32*)(p + 8 * 24 + 8);
                }
            #pragma unroll
            for (int m = 0; m < 2; m++)
                #pragma unroll
                for (int j = 0; j < 4; j++) {
                    #define TRM(xi, wi) mma16816(acc[m][j], a[wi][m][0], a[wi][m][1], a[wi][m][2], a[wi][m][3], bf0[xi][j], bf1[xi][j])
                    TRM(0, 0); TRM(0, 1); TRM(1, 0);
                    #undef TRM
                }
        }
        __syncthreads();
        if (step + 2 < 64) load_step(step + 2);

        if ((step & 15) == 15) {
            int t = step >> 4;
            int chb = ot * 64 + wn * 16 + r4;
            #pragma unroll
            for (int h = 0; h < 2; h++) {
                int cg = chb + h * 8;
                int cf = cg + 256;
                float bg0 = g_base[b * O_ + cg], bf0v = g_base[b * O_ + cf];
                float e0g = g_e0[b * O_ + cg], e0f = g_e0[b * O_ + cf];
                float e2g = g_e2[b * O_ + cg], e2f = g_e2[b * O_ + cf];
                #pragma unroll
                for (int j = 0; j < 4; j++)
                    #pragma unroll
                    for (int e = 0; e < 2; e++) {
                        int ll = wl * 32 + j * 8 + c2 + e;
                        int gl = l0 + ll;
                        float bg = bg0, bfv = bf0v;
                        if (gl == 0)      { bg -= e0g; bfv -= e0f; }
                        if (gl == L_ - 1) { bg -= e2g; bfv -= e2f; }
                        float yg = acc[0][j][h * 2 + e] * INV_SC + bg;
                        float yf = acc[1][j][h * 2 + e] * INV_SC + bfv;
                        int vi = j * 2 + e;
                        float vg = v[0][h][vi]; vg = vg + (yg - vg) / 1.2f;
                        float vf = v[1][h][vi]; vf = vf + (yf - vf) / 1.2f;
                        bool sg = vg >= 0.5f, sf = vf >= 0.5f;
                        v[0][h][vi] = sg ? 0.f : vg;
                        v[1][h][vi] = sf ? 0.f : vf;
                        su[ll * 72 + wn * 16 + r4 + h * 8] = sf ? one : zero;
                        sw_[ll * 72 + wn * 16 + r4 + h * 8] = (sf && sg) ? one : zero;
                    }
            }
            #pragma unroll
            for (int m = 0; m < 2; m++)
                #pragma unroll
                for (int j = 0; j < 4; j++)
                    #pragma unroll
                    for (int e = 0; e < 4; e++) acc[m][j][e] = 0.f;
            __syncthreads();
            {
                int row = tid >> 2, seg = tid & 3;
                __half* dst = g_s + ((size_t)(t * B_ + b) * L_ + l0 + row) * 512;
                uint4 a0 = *(uint4*)&su[row * 72 + seg * 16];
                uint4 a1 = *(uint4*)&su[row * 72 + seg * 16 + 8];
                uint4 b0 = *(uint4*)&sw_[row * 72 + seg * 16];
                uint4 b1 = *(uint4*)&sw_[row * 72 + seg * 16 + 8];
                *(uint4*)(dst + ot * 64 + seg * 16)           = a0;
                *(uint4*)(dst + ot * 64 + seg * 16 + 8)       = a1;
                *(uint4*)(dst + 256 + ot * 64 + seg * 16)     = b0;
                *(uint4*)(dst + 256 + ot * 64 + seg * 16 + 8) = b1;
            }
            __syncthreads();
        }
    }
}

// ---------------- output GEMM via mma.sync, 256-l tile ----------------
// grid (8 lt, 4 nt, 64 tb), 512 threads (16 warps: 4 n-groups x 4 l-groups)
// smem: S[2][256][40] @0 (2x20480), W[2][128][40] @40960 (2x10240) = 61440B
#define SMEM_OUT 61440
#define RS 40

__global__ void __launch_bounds__(512) k_out_mma(const float* __restrict__ x,
                                                 const float* __restrict__ b_skip,
                                                 const float* __restrict__ b_res,
                                                 float* __restrict__ out) {
    extern __shared__ __half smo[];
    const int lt = blockIdx.x, nt = blockIdx.y, tb = blockIdx.z;
    const int tid = threadIdx.x;
    const int wid = tid >> 5, lane = tid & 31;
    const int wn = wid >> 2;            // 0..3: n-group of 32
    const int wl = wid & 3;             // 0..3: l-group of 64
    const u32 sb = smem_u32(smo);

    const __half* gS = g_s + ((size_t)tb * L_ + lt * 256) * 512;
    const __half* gW = g_w2 + (size_t)(nt * 128) * 512;

    float acc[2][8][4];
    #pragma unroll
    for (int m = 0; m < 2; m++)
        #pragma unroll
        for (int j = 0; j < 8; j++)
            #pragma unroll
            for (int e = 0; e < 4; e++) acc[m][j][e] = 0.f;

    auto load_chunk = [&](int c) {
        int s = c & 1;
        int k0 = c * 32;
        u32 sS = sb + s * 20480;
        u32 sW = sb + 40960 + s * 10240;
        #pragma unroll
        for (int j = 0; j < 2; j++) {
            int u = tid + j * 512;            // 0..1023
            int r = u >> 2, c16 = u & 3;
            cp16(sS + (u32)(r * RS + c16 * 8) * 2, gS + (size_t)r * 512 + k0 + c16 * 8);
        }
        {
            int u = tid;                      // 0..511
            int r = u >> 2, c16 = u & 3;
            cp16(sW + (u32)(r * RS + c16 * 8) * 2, gW + (size_t)r * 512 + k0 + c16 * 8);
        }
        asm volatile("cp.async.commit_group;" ::: "memory");
    };

    load_chunk(0);
    load_chunk(1);

    const int r4 = lane >> 2, c2 = 2 * (lane & 3);

    #pragma unroll 1
    for (int c = 0; c < 16; c++) {
        if (c + 2 < 16) asm volatile("cp.async.wait_group 1;" ::: "memory");
        else            asm volatile("cp.async.wait_group 0;" ::: "memory");
        __syncthreads();
        int s = c & 1;
        const __half* S = smo + s * 10240;
        const __half* W = smo + 20480 + s * 5120;

        #pragma unroll
        for (int ks = 0; ks < 2; ks++) {
            int k0s = ks * 16;
            u32 bs0[8], bs1[8];
            #pragma unroll
            for (int j = 0; j < 8; j++) {
                int l = wl * 64 + j * 8 + r4;
                const __half* p = S + l * RS + k0s + c2;
                bs0[j] = *(const u32*)p;
                bs1[j] = *(const u32*)(p + 8);
            }
            #pragma unroll
            for (int m = 0; m < 2; m++) {
                int row = wn * 32 + m * 16 + r4;
                const __half* p = W + row * RS + k0s + c2;
                u32 a0 = *(const u32*)p;
                u32 a1 = *(const u32*)(p + 8 * RS);
                u32 a2 = *(const u32*)(p + 8);
                u32 a3 = *(const u32*)(p + 8 * RS + 8);
                #pragma unroll
                for (int j = 0; j < 8; j++)
                    mma16816(acc[m][j], a0, a1, a2, a3, bs0[j], bs1[j]);
            }
        }
        __syncthreads();
        if (c + 2 < 16) load_chunk(c + 2);
    }

    size_t base_tb = (size_t)tb * C_ * L_;
    #pragma unroll
    for (int m = 0; m < 2; m++) {
        #pragma unroll
        for (int j = 0; j < 8; j++) {
            int lg = lt * 256 + wl * 64 + j * 8 + c2;
            #pragma unroll
            for (int half = 0; half < 2; half++) {
                int ng = nt * 128 + wn * 32 + m * 16 + r4 + half * 8;
                float v0 = acc[m][j][half * 2], v1 = acc[m][j][half * 2 + 1];
                if (ng < 256) {
                    size_t idx = base_tb + (size_t)ng * L_ + lg;
                    float bias = b_res[ng];
                    float2 xv = *(const float2*)(x + idx);
                    *(float2*)(out + idx) = make_float2(v0 + xv.x + bias, v1 + xv.y + bias);
                } else {
                    int o = ng - 256;
                    size_t idx = base_tb + (size_t)o * L_ + lg;
                    float bias = b_skip[o];
                    *(float2*)(out + TBCL_ + idx) = make_float2(v0 + bias, v1 + bias);
                }
            }
        }
    }
}

extern "C" void kernel_launch(void* const* d_in, const int* in_sizes, int n_in,
                              void* d_out, int out_size) {
    const float* x      = (const float*)d_in[0];
    const int*   dstep  = (const int*)d_in[1];
    const float* w_emb1 = (const float*)d_in[2];
    const float* b_emb1 = (const float*)d_in[3];
    const float* w_emb2 = (const float*)d_in[4];
    const float* b_emb2 = (const float*)d_in[5];
    const float* w_proj = (const float*)d_in[6];
    const float* b_proj = (const float*)d_in[7];
    const float* w_conv = (const float*)d_in[8];
    const float* b_conv = (const float*)d_in[9];
    const float* w_skip = (const float*)d_in[10];
    const float* b_skip = (const float*)d_in[11];
    const float* w_res  = (const float*)d_in[12];
    const float* b_res  = (const float*)d_in[13];
    float* out = (float*)d_out;

    cudaFuncSetAttribute(k_out_mma, cudaFuncAttributeMaxDynamicSharedMemorySize, SMEM_OUT);
    cudaFuncSetAttribute(k_conv_mma, cudaFuncAttributeMaxDynamicSharedMemorySize, CONV_SMEM);

    k_prep<<<PREP_BLOCKS, 256>>>(x, dstep, w_emb1, b_emb1, w_emb2, b_emb2,
                                 w_proj, b_proj, w_conv, b_conv, w_skip, w_res);
    k_conv_mma<<<dim3(16, 4, 16), 512, CONV_SMEM>>>();
    k_out_mma<<<dim3(8, 4, 64), 512, SMEM_OUT>>>(x, b_skip, b_res, out);
}

// round 15
// speedup vs baseline: 1.0689x; 1.0689x over previous
#include <cuda_runtime.h>
#include <cuda_fp16.h>
#include <math.h>
#include <stdint.h>

#define T_ 4
#define B_ 16
#define C_ 256
#define L_ 2048
#define O_ 512
#define TBCL_ (T_*B_*C_*L_)
#define ZA 0.38079708f
#define ZB 0.55676994f
#define DZ (ZB - ZA)
#define XS 16.0f
#define WSC 128.0f
#define INV_SC (1.0f/2048.0f)

typedef uint32_t u32;

__device__ __forceinline__ u32 smem_u32(const void* p) {
    u32 a;
    asm("{ .reg .u64 t; cvta.to.shared.u64 t, %1; cvt.u32.u64 %0, t; }" : "=r"(a) : "l"(p));
    return a;
}
__device__ __forceinline__ void cp16(u32 dst, const void* src) {
    asm volatile("cp.async.cg.shared.global [%0], [%1], 16;" :: "r"(dst), "l"(src));
}
__device__ __forceinline__ void cp16z(u32 dst, const void* src, bool ok) {
    int sz = ok ? 16 : 0;
    asm volatile("cp.async.cg.shared.global [%0], [%1], 16, %2;" :: "r"(dst), "l"(src), "r"(sz));
}
__device__ __forceinline__ void mma16816(float* c, u32 a0, u32 a1, u32 a2, u32 a3, u32 b0, u32 b1) {
    asm volatile("mma.sync.aligned.m16n8k16.row.col.f32.f16.f16.f32 "
                 "{%0,%1,%2,%3},{%4,%5,%6,%7},{%8,%9},{%0,%1,%2,%3};"
                 : "+f"(c[0]), "+f"(c[1]), "+f"(c[2]), "+f"(c[3])
                 : "r"(a0), "r"(a1), "r"(a2), "r"(a3), "r"(b0), "r"(b1));
}

// ---- device scratch ----
__device__ __half g_s[(size_t)T_*B_*L_*512];   // spikes [tb][l][512] = [u(256)|w(256)]
__device__ __half g_xt[(size_t)T_*B_*16*L_*32];// x splits [tb][cs16][l][hi16|lo16], x16
__device__ __half g_w2[512 * 512];             // out-GEMM weights [n][512]
__device__ __half g_wcs[6 * 512 * 256];        // conv w splits [sp][sh][o][c], x128
__device__ float g_base[B_*O_];
__device__ float g_e0[B_*O_];
__device__ float g_e2[B_*O_];

// ---------------- fused prep kernel (block-range dispatch) ----------------
// [0,16): proj+econv ; [16,1040): w2build ; [1040,1552): wsplit ; [1552,34320): xsplit
#define PREP_BLOCKS 34320

__global__ void __launch_bounds__(256) k_prep(
    const float* __restrict__ x, const int* __restrict__ dstep,
    const float* __restrict__ w1, const float* __restrict__ b1,
    const float* __restrict__ w2, const float* __restrict__ b2,
    const float* __restrict__ wp, const float* __restrict__ bp,
    const float* __restrict__ w_conv, const float* __restrict__ b_conv,
    const float* __restrict__ w_skip, const float* __restrict__ w_res) {
    const int blk = blockIdx.x;
    const int tid = threadIdx.x;

    if (blk < 16) {                     // ---- proj + econv for batch b ----
        int b = blk, c = tid;
        __shared__ float h[C_], emb[C_], pr[C_];
        float ds = (float)dstep[b];
        float t1 = ds * w1[c] + b1[c];
        h[c] = t1 / (1.f + expf(-t1));
        __syncthreads();
        float e = b2[c];
        const float* w2r = w2 + c * C_;
        for (int j = 0; j < C_; j++) e += w2r[j] * h[j];
        __syncthreads();
        emb[c] = e;
        __syncthreads();
        float p = bp[c];
        const float* wpr = wp + c * C_;
        for (int j = 0; j < C_; j++) p += wpr[j] * emb[j];
        pr[c] = p;
        __syncthreads();
        // econv: warp-per-o, lanes parallel over c (coalesced 3KB/warp/o)
        int warp = tid >> 5, lane = tid & 31;
        float pv[8];
        #pragma unroll
        for (int e2i = 0; e2i < 8; e2i++) pv[e2i] = pr[lane * 8 + e2i];
        for (int oi = 0; oi < 64; oi++) {
            int o = warp * 64 + oi;
            const float* wr = w_conv + (size_t)o * 768 + lane * 24;
            float e0 = 0.f, e1 = 0.f, e2 = 0.f;
            #pragma unroll
            for (int e2i = 0; e2i < 8; e2i++) {
                float p2 = pv[e2i];
                e0 += wr[e2i * 3 + 0] * p2;
                e1 += wr[e2i * 3 + 1] * p2;
                e2 += wr[e2i * 3 + 2] * p2;
            }
            #pragma unroll
            for (int off = 16; off; off >>= 1) {
                e0 += __shfl_down_sync(~0u, e0, off);
                e1 += __shfl_down_sync(~0u, e1, off);
                e2 += __shfl_down_sync(~0u, e2, off);
            }
            if (lane == 0) {
                g_base[b * O_ + o] = e0 + e1 + e2 + b_conv[o];
                g_e0[b * O_ + o] = e0;
                g_e2[b * O_ + o] = e2;
            }
        }
    } else if (blk < 1040) {            // ---- w2build ----
        int i = (blk - 16) * 256 + tid;
        int n = i >> 9, kk = i & 511;
        int c = kk & 255, part = kk >> 8;
        float wv = (n < 256) ? w_res[n * C_ + c] : w_skip[(n - 256) * C_ + c];
        g_w2[n * 512 + kk] = __float2half((part ? DZ : ZA) * wv);
    } else if (blk < 1552) {            // ---- wsplit ----
        int i = (blk - 1040) * 256 + tid;
        int o = i >> 8, c = i & 255;
        #pragma unroll
        for (int k = 0; k < 3; k++) {
            float w = w_conv[(o * C_ + c) * 3 + k] * WSC;
            __half h1 = __float2half_rn(w);
            float r1 = w - __half2float(h1);
            __half h2 = __float2half_rn(r1);
            size_t base = ((size_t)k * 512 + o) * 256 + c;
            g_wcs[0 * 393216 + base] = h1;
            g_wcs[1 * 393216 + base] = h2;
        }
    } else {                            // ---- xsplit: c-chunked layout ----
        __shared__ float tile[32][33];
        int idx = blk - 1552;
        int lt = idx & 63, cb = (idx >> 6) & 7, tb = idx >> 9;
        int c0 = cb * 32, l0 = lt * 32;
        int tx = tid & 31, ty = tid >> 5;
        const float* xb = x + ((size_t)tb * C_ + c0) * L_ + l0;
        #pragma unroll
        for (int i = 0; i < 4; i++)
            tile[ty + i * 8][tx] = xb[(size_t)(ty + i * 8) * L_ + tx];   // tile[c][l]
        __syncthreads();
        // write: thread -> (part, grp, l, csl); uint4 = 8 halves, fully coalesced
        int part = tid & 1, grp = (tid >> 1) & 1, l = (tid >> 2) & 31, csl = tid >> 7;
        int cs = (c0 >> 4) + csl;
        __half hv[8];
        #pragma unroll
        for (int e = 0; e < 8; e++) {
            float v = tile[csl * 16 + part * 8 + e][l] * XS;
            __half h1 = __float2half_rn(v);
            hv[e] = grp ? __float2half_rn(v - __half2float(h1)) : h1;
        }
        __half* dst = g_xt + (((size_t)tb * 16 + cs) * L_ + l0 + l) * 32 + grp * 16 + part * 8;
        *(uint4*)dst = *(uint4*)hv;
    }
}

// ---------------- conv1d + LIF via HMMA (fp16 2x2 split, 3 terms) ----------------
// 128-l tile, 512 threads, 1 CTA/SM. grid (16 lt, 4 ot, 16 b).
// stage: ws[6 q][128 m][24 halves] = 36864B ; xs[130 l][40 halves] = 10400B
#define WS_SZ 36864
#define CSTAGE 47264
#define CONV_SMEM (2*CSTAGE + 2*18432)

__global__ void __launch_bounds__(512, 1) k_conv_mma() {
    extern __shared__ char sm[];
    const u32 sb = smem_u32(sm);
    const int lt = blockIdx.x, ot = blockIdx.y, b = blockIdx.z;
    const int l0 = lt * 128;
    const int tid = threadIdx.x, wid = tid >> 5, lane = tid & 31;
    const int wn = wid >> 2, wl = wid & 3;
    const int r4 = lane >> 2, c2 = (lane & 3) * 2;

    __half* su  = (__half*)(sm + 2 * CSTAGE);
    __half* sw_ = (__half*)(sm + 2 * CSTAGE + 18432);

    auto load_step = [&](int step) {
        int t = step >> 4, s = step & 1;
        int cc = (step & 15) << 4;
        u32 wsb = sb + s * CSTAGE;
        #pragma unroll
        for (int j = 0; j < 3; j++) {
            int idx = tid + j * 512;
            int c16 = idx & 1;
            int m = (idx >> 1) & 127;
            int q = idx >> 8;
            int sh = q >> 1, sp = q & 1;
            int o = (m < 64) ? (ot * 64 + m) : (256 + ot * 64 + m - 64);
            const __half* src = g_wcs + (((size_t)(sp * 3 + sh) * 512 + o) << 8) + cc + c16 * 8;
            cp16(wsb + (u32)((q * 128 + m) * 48 + c16 * 16), src);
        }
        // x tile: contiguous rows from c-chunked g_xt
        const __half* xb = g_xt + ((size_t)(t * B_ + b) * 16 + (step & 15)) * L_ * 32;
        u32 xsb = sb + s * CSTAGE + WS_SZ;
        #pragma unroll
        for (int j = 0; j < 2; j++) {
            int u = tid + j * 512;
            if (u < 520) {
                int li = u >> 2, q = u & 3;      // q*8: 0,8 = hi ; 16,24 = lo
                int gl = l0 - 1 + li;
                bool ok = (gl >= 0 && gl < L_);
                const __half* src = xb + (size_t)(ok ? gl : 0) * 32 + q * 8;
                cp16z(xsb + (u32)((li * 40 + q * 8) * 2), src, ok);
            }
        }
        asm volatile("cp.async.commit_group;" ::: "memory");
    };

    float acc[2][4][4];
    float v[2][2][8];
    #pragma unroll
    for (int m = 0; m < 2; m++)
        #pragma unroll
        for (int j = 0; j < 4; j++)
            #pragma unroll
            for (int e = 0; e < 4; e++) acc[m][j][e] = 0.f;
    #pragma unroll
    for (int g = 0; g < 2; g++)
        #pragma unroll
        for (int h = 0; h < 2; h++)
            #pragma unroll
            for (int e = 0; e < 8; e++) v[g][h][e] = 0.f;

    load_step(0);
    load_step(1);

    const __half one = __float2half(1.f), zero = __float2half(0.f);

    #pragma unroll 1
    for (int step = 0; step < 64; step++) {
        if (step < 62) asm volatile("cp.async.wait_group 1;" ::: "memory");
        else           asm volatile("cp.async.wait_group 0;" ::: "memory");
        __syncthreads();
        int s = step & 1;
        const char* wsb = sm + s * CSTAGE;
        const __half* xs = (const __half*)(sm + s * CSTAGE + WS_SZ);

        #pragma unroll
        for (int sh = 0; sh < 3; sh++) {
            u32 bf0[2][4], bf1[2][4];
            #pragma unroll
            for (int sp = 0; sp < 2; sp++)
                #pragma unroll
                for (int j = 0; j < 4; j++) {
                    const __half* p = xs + (wl * 32 + j * 8 + r4 + sh) * 40 + sp * 16 + c2;
                    bf0[sp][j] = *(const u32*)p;
                    bf1[sp][j] = *(const u32*)(p + 8);
                }
            u32 a[2][2][4];
            #pragma unroll
            for (int sp = 0; sp < 2; sp++)
                #pragma unroll
                for (int m = 0; m < 2; m++) {
                    const __half* p = (const __half*)(wsb + ((sh * 2 + sp) * 128 + m * 64 + wn * 16 + r4) * 48) + c2;
                    a[sp][m][0] = *(const u32*)p;
                    a[sp][m][1] = *(const u32*)(p + 8 * 24);
                    a[sp][m][2] = *(const u32*)(p + 8);
                    a[sp][m][3] = *(const u32*)(p + 8 * 24 + 8);
                }
            #pragma unroll
            for (int m = 0; m < 2; m++)
                #pragma unroll
                for (int j = 0; j < 4; j++) {
                    #define TRM(xi, wi) mma16816(acc[m][j], a[wi][m][0], a[wi][m][1], a[wi][m][2], a[wi][m][3], bf0[xi][j], bf1[xi][j])
                    TRM(0, 0); TRM(0, 1); TRM(1, 0);
                    #undef TRM
                }
        }
        __syncthreads();
        if (step + 2 < 64) load_step(step + 2);

        if ((step & 15) == 15) {
            int t = step >> 4;
            int chb = ot * 64 + wn * 16 + r4;
            #pragma unroll
            for (int h = 0; h < 2; h++) {
                int cg = chb + h * 8;
                int cf = cg + 256;
                float bg0 = g_base[b * O_ + cg], bf0v = g_base[b * O_ + cf];
                float e0g = g_e0[b * O_ + cg], e0f = g_e0[b * O_ + cf];
                float e2g = g_e2[b * O_ + cg], e2f = g_e2[b * O_ + cf];
                #pragma unroll
                for (int j = 0; j < 4; j++)
                    #pragma unroll
                    for (int e = 0; e < 2; e++) {
                        int ll = wl * 32 + j * 8 + c2 + e;
                        int gl = l0 + ll;
                        float bg = bg0, bfv = bf0v;
                        if (gl == 0)      { bg -= e0g; bfv -= e0f; }
                        if (gl == L_ - 1) { bg -= e2g; bfv -= e2f; }
                        float yg = acc[0][j][h * 2 + e] * INV_SC + bg;
                        float yf = acc[1][j][h * 2 + e] * INV_SC + bfv;
                        int vi = j * 2 + e;
                        float vg = v[0][h][vi]; vg = vg + (yg - vg) / 1.2f;
                        float vf = v[1][h][vi]; vf = vf + (yf - vf) / 1.2f;
                        bool sg = vg >= 0.5f, sf = vf >= 0.5f;
                        v[0][h][vi] = sg ? 0.f : vg;
                        v[1][h][vi] = sf ? 0.f : vf;
                        su[ll * 72 + wn * 16 + r4 + h * 8] = sf ? one : zero;
                        sw_[ll * 72 + wn * 16 + r4 + h * 8] = (sf && sg) ? one : zero;
                    }
            }
            #pragma unroll
            for (int m = 0; m < 2; m++)
                #pragma unroll
                for (int j = 0; j < 4; j++)
                    #pragma unroll
                    for (int e = 0; e < 4; e++) acc[m][j][e] = 0.f;
            __syncthreads();
            {
                int row = tid >> 2, seg = tid & 3;
                __half* dst = g_s + ((size_t)(t * B_ + b) * L_ + l0 + row) * 512;
                uint4 a0 = *(uint4*)&su[row * 72 + seg * 16];
                uint4 a1 = *(uint4*)&su[row * 72 + seg * 16 + 8];
                uint4 b0 = *(uint4*)&sw_[row * 72 + seg * 16];
                uint4 b1 = *(uint4*)&sw_[row * 72 + seg * 16 + 8];
                *(uint4*)(dst + ot * 64 + seg * 16)           = a0;
                *(uint4*)(dst + ot * 64 + seg * 16 + 8)       = a1;
                *(uint4*)(dst + 256 + ot * 64 + seg * 16)     = b0;
                *(uint4*)(dst + 256 + ot * 64 + seg * 16 + 8) = b1;
            }
            __syncthreads();
        }
    }
}

// ---------------- output GEMM via mma.sync, 256-l tile ----------------
// grid (8 lt, 4 nt, 64 tb), 512 threads (16 warps)
#define SMEM_OUT 61440
#define RS 40

__global__ void __launch_bounds__(512) k_out_mma(const float* __restrict__ x,
                                                 const float* __restrict__ b_skip,
                                                 const float* __restrict__ b_res,
                                                 float* __restrict__ out) {
    extern __shared__ __half smo[];
    const int lt = blockIdx.x, nt = blockIdx.y, tb = blockIdx.z;
    const int tid = threadIdx.x;
    const int wid = tid >> 5, lane = tid & 31;
    const int wn = wid >> 2;
    const int wl = wid & 3;
    const u32 sb = smem_u32(smo);

    const __half* gS = g_s + ((size_t)tb * L_ + lt * 256) * 512;
    const __half* gW = g_w2 + (size_t)(nt * 128) * 512;

    float acc[2][8][4];
    #pragma unroll
    for (int m = 0; m < 2; m++)
        #pragma unroll
        for (int j = 0; j < 8; j++)
            #pragma unroll
            for (int e = 0; e < 4; e++) acc[m][j][e] = 0.f;

    auto load_chunk = [&](int c) {
        int s = c & 1;
        int k0 = c * 32;
        u32 sS = sb + s * 20480;
        u32 sW = sb + 40960 + s * 10240;
        #pragma unroll
        for (int j = 0; j < 2; j++) {
            int u = tid + j * 512;
            int r = u >> 2, c16 = u & 3;
            cp16(sS + (u32)(r * RS + c16 * 8) * 2, gS + (size_t)r * 512 + k0 + c16 * 8);
        }
        {
            int u = tid;
            int r = u >> 2, c16 = u & 3;
            cp16(sW + (u32)(r * RS + c16 * 8) * 2, gW + (size_t)r * 512 + k0 + c16 * 8);
        }
        asm volatile("cp.async.commit_group;" ::: "memory");
    };

    load_chunk(0);
    load_chunk(1);

    const int r4 = lane >> 2, c2 = 2 * (lane & 3);

    #pragma unroll 1
    for (int c = 0; c < 16; c++) {
        if (c + 2 < 16) asm volatile("cp.async.wait_group 1;" ::: "memory");
        else            asm volatile("cp.async.wait_group 0;" ::: "memory");
        __syncthreads();
        int s = c & 1;
        const __half* S = smo + s * 10240;
        const __half* W = smo + 20480 + s * 5120;

        #pragma unroll
        for (int ks = 0; ks < 2; ks++) {
            int k0s = ks * 16;
            u32 bs0[8], bs1[8];
            #pragma unroll
            for (int j = 0; j < 8; j++) {
                int l = wl * 64 + j * 8 + r4;
                const __half* p = S + l * RS + k0s + c2;
                bs0[j] = *(const u32*)p;
                bs1[j] = *(const u32*)(p + 8);
            }
            #pragma unroll
            for (int m = 0; m < 2; m++) {
                int row = wn * 32 + m * 16 + r4;
                const __half* p = W + row * RS + k0s + c2;
                u32 a0 = *(const u32*)p;
                u32 a1 = *(const u32*)(p + 8 * RS);
                u32 a2 = *(const u32*)(p + 8);
                u32 a3 = *(const u32*)(p + 8 * RS + 8);
                #pragma unroll
                for (int j = 0; j < 8; j++)
                    mma16816(acc[m][j], a0, a1, a2, a3, bs0[j], bs1[j]);
            }
        }
        __syncthreads();
        if (c + 2 < 16) load_chunk(c + 2);
    }

    size_t base_tb = (size_t)tb * C_ * L_;
    #pragma unroll
    for (int m = 0; m < 2; m++) {
        #pragma unroll
        for (int j = 0; j < 8; j++) {
            int lg = lt * 256 + wl * 64 + j * 8 + c2;
            #pragma unroll
            for (int half = 0; half < 2; half++) {
                int ng = nt * 128 + wn * 32 + m * 16 + r4 + half * 8;
                float v0 = acc[m][j][half * 2], v1 = acc[m][j][half * 2 + 1];
                if (ng < 256) {
                    size_t idx = base_tb + (size_t)ng * L_ + lg;
                    float bias = b_res[ng];
                    float2 xv = *(const float2*)(x + idx);
                    *(float2*)(out + idx) = make_float2(v0 + xv.x + bias, v1 + xv.y + bias);
                } else {
                    int o = ng - 256;
                    size_t idx = base_tb + (size_t)o * L_ + lg;
                    float bias = b_skip[o];
                    *(float2*)(out + TBCL_ + idx) = make_float2(v0 + bias, v1 + bias);
                }
            }
        }
    }
}

extern "C" void kernel_launch(void* const* d_in, const int* in_sizes, int n_in,
                              void* d_out, int out_size) {
    const float* x      = (const float*)d_in[0];
    const int*   dstep  = (const int*)d_in[1];
    const float* w_emb1 = (const float*)d_in[2];
    const float* b_emb1 = (const float*)d_in[3];
    const float* w_emb2 = (const float*)d_in[4];
    const float* b_emb2 = (const float*)d_in[5];
    const float* w_proj = (const float*)d_in[6];
    const float* b_proj = (const float*)d_in[7];
    const float* w_conv = (const float*)d_in[8];
    const float* b_conv = (const float*)d_in[9];
    const float* w_skip = (const float*)d_in[10];
    const float* b_skip = (const float*)d_in[11];
    const float* w_res  = (const float*)d_in[12];
    const float* b_res  = (const float*)d_in[13];
    float* out = (float*)d_out;

    cudaFuncSetAttribute(k_out_mma, cudaFuncAttributeMaxDynamicSharedMemorySize, SMEM_OUT);
    cudaFuncSetAttribute(k_conv_mma, cudaFuncAttributeMaxDynamicSharedMemorySize, CONV_SMEM);

    k_prep<<<PREP_BLOCKS, 256>>>(x, dstep, w_emb1, b_emb1, w_emb2, b_emb2,
                                 w_proj, b_proj, w_conv, b_conv, w_skip, w_res);
    k_conv_mma<<<dim3(16, 4, 16), 512, CONV_SMEM>>>();
    k_out_mma<<<dim3(8, 4, 64), 512, SMEM_OUT>>>(x, b_skip, b_res, out);
}